// round 15
// baseline (speedup 1.0000x reference)
#include <cuda_runtime.h>

// LogSig_var: depth-2 log-signature over 64 segments.
// inp: (B, T, 12) fp32, length: (B,) int32 -> out: (B, 64, 78) fp32
//
// 8 blocks per batch (grid = 8B), TPB=128 (4 warps). Block q handles segments
// [8q, 8q+8), staging only its row slice (~L/8). Warp = pair-group (uniform
// switch). Lane = (h*8 + segLocal): h in 0..3 quarters each segment's steps;
// partials combine with shfl_xor(8) + shfl_xor(16). Lane h==0 writes.

#define D_CH 12
#define NSEG 64
#define TPB 128

__host__ __device__ constexpr int pairI(int p) {
    int i = 0, rem = p;
    while (rem >= 11 - i) { rem -= 11 - i; i++; }
    return i;
}
__host__ __device__ constexpr int pairJ(int p) {
    int i = 0, rem = p;
    while (rem >= 11 - i) { rem -= 11 - i; i++; }
    return i + 1 + rem;
}

// Monotone skew every 32 local rows: no overlap; decorrelates large row strides.
__device__ __forceinline__ int srow(int row) {
    return row * 12 + (row >> 5) * 4;
}

struct Row { float v[D_CH]; };

__device__ __forceinline__ void loadRow(const float* sX, int row, Row& r) {
    int base = srow(row);
    float4 a = *(const float4*)(sX + base);
    float4 b = *(const float4*)(sX + base + 4);
    float4 c = *(const float4*)(sX + base + 8);
    r.v[0]=a.x; r.v[1]=a.y; r.v[2]=a.z;  r.v[3]=a.w;
    r.v[4]=b.x; r.v[5]=b.y; r.v[6]=b.z;  r.v[7]=b.w;
    r.v[8]=c.x; r.v[9]=c.y; r.v[10]=c.z; r.v[11]=c.w;
}

// Template recursion: pair indices are compile-time literals -> registers only.
template<int P, int PEND>
struct Pairs {
    static __device__ __forceinline__ void acc(const Row& cur, const Row& nxt, float* a) {
        constexpr int i = pairI(P);
        constexpr int j = pairJ(P);
        float t = a[0];
        t = fmaf(cur.v[i],  nxt.v[j], t);
        t = fmaf(-cur.v[j], nxt.v[i], t);
        a[0] = t;
        Pairs<P + 1, PEND>::acc(cur, nxt, a + 1);
    }
    static __device__ __forceinline__ void comb(float* a) {
        a[0] += __shfl_xor_sync(0xFFFFFFFFu, a[0], 8);
        a[0] += __shfl_xor_sync(0xFFFFFFFFu, a[0], 16);
        Pairs<P + 1, PEND>::comb(a + 1);
    }
    static __device__ __forceinline__ void out(float* ob, const Row& xa, const Row& xb,
                                               const float* a) {
        constexpr int i = pairI(P);
        constexpr int j = pairJ(P);
        float cross = xa.v[i] * xb.v[j] - xa.v[j] * xb.v[i];
        ob[D_CH + P] = 0.5f * (a[0] - cross);
        Pairs<P + 1, PEND>::out(ob, xa, xb, a + 1);
    }
};
template<int P>
struct Pairs<P, P> {
    static __device__ __forceinline__ void acc(const Row&, const Row&, float*) {}
    static __device__ __forceinline__ void comb(float*) {}
    static __device__ __forceinline__ void out(float*, const Row&, const Row&, const float*) {}
};

// Sum cross terms for t in [t0, t1); rows indexed relative to rowLo.
template<bool EXPAND, int P0, int P1>
__device__ __forceinline__ void accum_range(const float* sX, int t0, int t1,
                                            int k, int rowLo, float* acc) {
    if (t0 >= t1) return;
    Row x, y;
    loadRow(sX, (EXPAND ? (t0 / k) : t0) - rowLo, x);
    int t = t0;
    for (;;) {
        loadRow(sX, (EXPAND ? ((t + 1) / k) : (t + 1)) - rowLo, y);
        Pairs<P0, P1>::acc(x, y, acc);
        if (++t >= t1) return;
        loadRow(sX, (EXPAND ? ((t + 1) / k) : (t + 1)) - rowLo, x);
        Pairs<P0, P1>::acc(y, x, acc);
        if (++t >= t1) return;
    }
}

template<bool EXPAND, int P0, int P1, bool WRITE_INC>
__device__ __forceinline__ void do_group(const float* sX, int a, int b, int k,
                                         int rowLo, float* ob, int h) {
    float acc[P1 - P0];
#pragma unroll
    for (int q = 0; q < P1 - P0; q++) acc[q] = 0.0f;

    // Quarter the steps [a,b): t(h) = a + h*n/4 tiles the range exactly.
    const int n  = b - a;
    const int t0 = a + ((h * n) >> 2);
    const int t1 = a + (((h + 1) * n) >> 2);
    accum_range<EXPAND, P0, P1>(sX, t0, t1, k, rowLo, acc);

    Pairs<P0, P1>::comb(acc);

    if (h == 0) {
        Row xa, xb;
        loadRow(sX, (EXPAND ? (a / k) : a) - rowLo, xa);
        loadRow(sX, (EXPAND ? (b / k) : b) - rowLo, xb);
        if (WRITE_INC) {
#pragma unroll
            for (int c = 0; c < D_CH; c++) ob[c] = xb.v[c] - xa.v[c];
        }
        Pairs<P0, P1>::out(ob, xa, xb, acc);
    }
}

__global__ __launch_bounds__(TPB, 8)
void logsig_kernel(const float* __restrict__ inp, const int* __restrict__ length,
                   float* __restrict__ out, int T) {
    extern __shared__ float sX[];
    const int blk = blockIdx.x >> 3;        // batch
    const int qb  = blockIdx.x & 7;         // segment-eighth 0..7
    const int L = length[blk];

    const bool expand = (L < NSEG + 1);
    const int k    = expand ? (NSEG / L + 1) : 1;
    const int Leff = expand ? (k * L) : L;
    const float Lm1 = (float)(Leff - 1);
    const int s0 = qb << 3;                 // first segment of this block

    // Block-level step range -> row range to stage.
    // tv_j = round(1 + j*(Leff-1)/64); exact fp32, rintf == jnp.round.
    const int aB = (int)rintf(1.0f + ((float)s0       * Lm1) * (1.0f / 64.0f)) - 1;
    const int bB = (int)rintf(1.0f + ((float)(s0 + 8) * Lm1) * (1.0f / 64.0f)) - 1;
    const int rowLo = expand ? 0 : aB;
    const int rowHi = expand ? (L - 1) : bB;

    // Stage rows [rowLo, rowHi] (coalesced float4; rows are 3 quads).
    const float4* Xg = (const float4*)(inp + (size_t)blk * T * D_CH);
    const int n4 = (rowHi - rowLo + 1) * 3;
    const int g0 = rowLo * 3;
    for (int i = threadIdx.x; i < n4; i += TPB) {
        float4 v = Xg[g0 + i];
        int row = i / 3;
        int q = i - row * 3;
        *(float4*)&sX[row * 12 + (row >> 5) * 4 + q * 4] = v;
    }
    __syncthreads();

    const int wid  = threadIdx.x >> 5;      // 0..3 = pair-group (warp-uniform)
    const int lane = threadIdx.x & 31;
    const int h = lane >> 3;                // step-quarter 0..3
    const int s = s0 + (lane & 7);          // segment

    const int a  = (int)rintf(1.0f + ((float)s       * Lm1) * (1.0f / 64.0f)) - 1;
    const int bb = (int)rintf(1.0f + ((float)(s + 1) * Lm1) * (1.0f / 64.0f)) - 1;

    float* ob = out + ((size_t)blk * NSEG + s) * 78;

    if (!expand) {
        switch (wid) {   // uniform across the warp
            case 0:  do_group<false,  0, 17, true >(sX, a, bb, 1, rowLo, ob, h); break;
            case 1:  do_group<false, 17, 34, false>(sX, a, bb, 1, rowLo, ob, h); break;
            case 2:  do_group<false, 34, 50, false>(sX, a, bb, 1, rowLo, ob, h); break;
            default: do_group<false, 50, 66, false>(sX, a, bb, 1, rowLo, ob, h); break;
        }
    } else {
        switch (wid) {
            case 0:  do_group<true,  0, 17, true >(sX, a, bb, k, rowLo, ob, h); break;
            case 1:  do_group<true, 17, 34, false>(sX, a, bb, k, rowLo, ob, h); break;
            case 2:  do_group<true, 34, 50, false>(sX, a, bb, k, rowLo, ob, h); break;
            default: do_group<true, 50, 66, false>(sX, a, bb, k, rowLo, ob, h); break;
        }
    }
}

extern "C" void kernel_launch(void* const* d_in, const int* in_sizes, int n_in,
                              void* d_out, int out_size) {
    const float* inp    = (const float*)d_in[0];
    const int*   length = (const int*)d_in[1];
    float*       out    = (float*)d_out;

    const int B = in_sizes[1];
    const int T = in_sizes[0] / (B * D_CH);

    // Max staged rows per block: ~T/8 + margin (expand caps at 64 rows anyway).
    const int maxRows = T / 8 + 8;
    const size_t smemBytes =
        (size_t)(maxRows * 12 + (maxRows >> 5) * 4 + 16) * sizeof(float);

    cudaFuncSetAttribute(logsig_kernel,
                         cudaFuncAttributeMaxDynamicSharedMemorySize,
                         (int)smemBytes);

    logsig_kernel<<<B * 8, TPB, smemBytes>>>(inp, length, out, T);
}

// round 17
// speedup vs baseline: 1.8047x; 1.8047x over previous
#include <cuda_runtime.h>
#include <cstdint>

// LogSig_var: depth-2 log-signature over 64 segments.
// inp: (B, T, 12) fp32, length: (B,) int32 -> out: (B, 64, 78) fp32
//
// 4 blocks per batch (grid = 4B), TPB=128. Block q handles segments
// [16q, 16q+16), staging only rows [rowLo, rowHi] (~L/4) via cp.async
// (LDGSTS: no LDG->STS data dependency, full MLP, one wait).
// Warp = pair-group (uniform switch). Lane = (segment 0..15, step-half h);
// halves combine with shfl_xor(16).

#define D_CH 12
#define NSEG 64
#define TPB 128

__host__ __device__ constexpr int pairI(int p) {
    int i = 0, rem = p;
    while (rem >= 11 - i) { rem -= 11 - i; i++; }
    return i;
}
__host__ __device__ constexpr int pairJ(int p) {
    int i = 0, rem = p;
    while (rem >= 11 - i) { rem -= 11 - i; i++; }
    return i + 1 + rem;
}

// Monotone skew every 32 local rows: no overlap; decorrelates lane row strides.
__device__ __forceinline__ int srow(int row) {
    return row * 12 + (row >> 5) * 4;
}

struct Row { float v[D_CH]; };

__device__ __forceinline__ void loadRow(const float* sX, int row, Row& r) {
    int base = srow(row);
    float4 a = *(const float4*)(sX + base);
    float4 b = *(const float4*)(sX + base + 4);
    float4 c = *(const float4*)(sX + base + 8);
    r.v[0]=a.x; r.v[1]=a.y; r.v[2]=a.z;  r.v[3]=a.w;
    r.v[4]=b.x; r.v[5]=b.y; r.v[6]=b.z;  r.v[7]=b.w;
    r.v[8]=c.x; r.v[9]=c.y; r.v[10]=c.z; r.v[11]=c.w;
}

// Template recursion: pair indices are compile-time literals -> registers only.
template<int P, int PEND>
struct Pairs {
    static __device__ __forceinline__ void acc(const Row& cur, const Row& nxt, float* a) {
        constexpr int i = pairI(P);
        constexpr int j = pairJ(P);
        float t = a[0];
        t = fmaf(cur.v[i],  nxt.v[j], t);
        t = fmaf(-cur.v[j], nxt.v[i], t);
        a[0] = t;
        Pairs<P + 1, PEND>::acc(cur, nxt, a + 1);
    }
    static __device__ __forceinline__ void comb(float* a) {
        a[0] += __shfl_xor_sync(0xFFFFFFFFu, a[0], 16);
        Pairs<P + 1, PEND>::comb(a + 1);
    }
    static __device__ __forceinline__ void out(float* ob, const Row& xa, const Row& xb,
                                               const float* a) {
        constexpr int i = pairI(P);
        constexpr int j = pairJ(P);
        float cross = xa.v[i] * xb.v[j] - xa.v[j] * xb.v[i];
        ob[D_CH + P] = 0.5f * (a[0] - cross);
        Pairs<P + 1, PEND>::out(ob, xa, xb, a + 1);
    }
};
template<int P>
struct Pairs<P, P> {
    static __device__ __forceinline__ void acc(const Row&, const Row&, float*) {}
    static __device__ __forceinline__ void comb(float*) {}
    static __device__ __forceinline__ void out(float*, const Row&, const Row&, const float*) {}
};

// Sum cross terms for t in [t0, t1); rows indexed relative to rowLo.
template<bool EXPAND, int P0, int P1>
__device__ __forceinline__ void accum_range(const float* sX, int t0, int t1,
                                            int k, int rowLo, float* acc) {
    if (t0 >= t1) return;
    Row x, y;
    loadRow(sX, (EXPAND ? (t0 / k) : t0) - rowLo, x);
    int t = t0;
    for (;;) {
        loadRow(sX, (EXPAND ? ((t + 1) / k) : (t + 1)) - rowLo, y);
        Pairs<P0, P1>::acc(x, y, acc);
        if (++t >= t1) return;
        loadRow(sX, (EXPAND ? ((t + 1) / k) : (t + 1)) - rowLo, x);
        Pairs<P0, P1>::acc(y, x, acc);
        if (++t >= t1) return;
    }
}

template<bool EXPAND, int P0, int P1, bool WRITE_INC>
__device__ __forceinline__ void do_group(const float* sX, int a, int b, int k,
                                         int rowLo, float* ob, int h) {
    float acc[P1 - P0];
#pragma unroll
    for (int q = 0; q < P1 - P0; q++) acc[q] = 0.0f;

    // Split steps [a,b) between h=0 and h=1 (lanes 16 apart).
    const int m = a + ((b - a + 1) >> 1);
    accum_range<EXPAND, P0, P1>(sX, h ? m : a, h ? b : m, k, rowLo, acc);

    Pairs<P0, P1>::comb(acc);

    if (h == 0) {
        Row xa, xb;
        loadRow(sX, (EXPAND ? (a / k) : a) - rowLo, xa);
        loadRow(sX, (EXPAND ? (b / k) : b) - rowLo, xb);
        if (WRITE_INC) {
#pragma unroll
            for (int c = 0; c < D_CH; c++) ob[c] = xb.v[c] - xa.v[c];
        }
        Pairs<P0, P1>::out(ob, xa, xb, acc);
    }
}

__global__ __launch_bounds__(TPB, 6)
void logsig_kernel(const float* __restrict__ inp, const int* __restrict__ length,
                   float* __restrict__ out, int T) {
    extern __shared__ float sX[];
    const int blk = blockIdx.x >> 2;        // batch
    const int qb  = blockIdx.x & 3;         // segment-quarter 0..3
    const int L = __ldg(length + blk);

    const bool expand = (L < NSEG + 1);
    const int k    = expand ? (NSEG / L + 1) : 1;
    const int Leff = expand ? (k * L) : L;
    const float Lm1 = (float)(Leff - 1);
    const int s0 = qb << 4;                 // first segment of this block

    // Block-level step range -> row range to stage.
    // tv_j = round(1 + j*(Leff-1)/64); exact fp32, rintf == jnp.round.
    const int aB = (int)rintf(1.0f + ((float)s0        * Lm1) * (1.0f / 64.0f)) - 1;
    const int bB = (int)rintf(1.0f + ((float)(s0 + 16) * Lm1) * (1.0f / 64.0f)) - 1;
    const int rowLo = expand ? 0 : aB;
    const int rowHi = expand ? (L - 1) : bB;

    // Stage rows [rowLo, rowHi] via cp.async: no LDG->STS data dependency,
    // all copies in flight at once, single wait. 16B granules, swizzled dst.
    {
        const float4* Xg = (const float4*)(inp + (size_t)blk * T * D_CH);
        const int n4 = (rowHi - rowLo + 1) * 3;
        const float4* src = Xg + rowLo * 3;
        for (int i = threadIdx.x; i < n4; i += TPB) {
            int row = i / 3;
            int q = i - row * 3;
            unsigned int dst = (unsigned int)__cvta_generic_to_shared(
                &sX[row * 12 + (row >> 5) * 4 + q * 4]);
            asm volatile("cp.async.cg.shared.global [%0], [%1], 16;"
                         :: "r"(dst), "l"(src + i) : "memory");
        }
        asm volatile("cp.async.commit_group;" ::: "memory");
        asm volatile("cp.async.wait_group 0;" ::: "memory");
    }
    __syncthreads();

    const int wid  = threadIdx.x >> 5;      // 0..3 = pair-group (warp-uniform)
    const int lane = threadIdx.x & 31;
    const int h = lane >> 4;                // step-half
    const int s = s0 + (lane & 15);         // segment

    const int a  = (int)rintf(1.0f + ((float)s       * Lm1) * (1.0f / 64.0f)) - 1;
    const int bb = (int)rintf(1.0f + ((float)(s + 1) * Lm1) * (1.0f / 64.0f)) - 1;

    float* ob = out + ((size_t)blk * NSEG + s) * 78;

    if (!expand) {
        switch (wid) {   // uniform across the warp
            case 0:  do_group<false,  0, 17, true >(sX, a, bb, 1, rowLo, ob, h); break;
            case 1:  do_group<false, 17, 34, false>(sX, a, bb, 1, rowLo, ob, h); break;
            case 2:  do_group<false, 34, 50, false>(sX, a, bb, 1, rowLo, ob, h); break;
            default: do_group<false, 50, 66, false>(sX, a, bb, 1, rowLo, ob, h); break;
        }
    } else {
        switch (wid) {
            case 0:  do_group<true,  0, 17, true >(sX, a, bb, k, rowLo, ob, h); break;
            case 1:  do_group<true, 17, 34, false>(sX, a, bb, k, rowLo, ob, h); break;
            case 2:  do_group<true, 34, 50, false>(sX, a, bb, k, rowLo, ob, h); break;
            default: do_group<true, 50, 66, false>(sX, a, bb, k, rowLo, ob, h); break;
        }
    }
}

extern "C" void kernel_launch(void* const* d_in, const int* in_sizes, int n_in,
                              void* d_out, int out_size) {
    const float* inp    = (const float*)d_in[0];
    const int*   length = (const int*)d_in[1];
    float*       out    = (float*)d_out;

    const int B = in_sizes[1];
    const int T = in_sizes[0] / (B * D_CH);

    // Max staged rows per block: ~T/4 + margin, with skew.
    const int maxRows = T / 4 + 4;
    const size_t smemBytes =
        (size_t)(maxRows * 12 + (maxRows >> 5) * 4 + 16) * sizeof(float);

    cudaFuncSetAttribute(logsig_kernel,
                         cudaFuncAttributeMaxDynamicSharedMemorySize,
                         (int)smemBytes);

    logsig_kernel<<<B * 4, TPB, smemBytes>>>(inp, length, out, T);
}